// round 13
// baseline (speedup 1.0000x reference)
#include <cuda_runtime.h>

// embedding_pooling: out[b, (c-1)*256 + d] = relu(max_{l: label[b,l]==c} x[b,l,d]), empty->0
//  - relu + empty-case == fmax chain initialized at 0.
//  - Labels are int32 on device (proven R2 fail / R3 pass).
//
// Page-dense gather: CTA = quarter of a batch row (128 rows = 128KB), 5 warps,
// warp w owns class w+1. Each warp ballot-gathers its own row list (no block
// syncs at all) and streams it; because warp k's j-th row sits near position
// 6j of the quarter, the 5 warps' requests form a sliding ~8KB window that
// touches every non-zero row in order -> near-linear DRAM page behavior while
// still skipping label-0 rows (107MB instead of 128MB).
// Partials go to a static scratch; a tiny second kernel folds the 4 quarters.

#define BATCH 256
#define LSEQ  512
#define DDIM  256
#define NC    5
#define QROWS 128
#define NQ    (LSEQ / QROWS)          // 4
#define GRID_MAIN (BATCH * NQ)        // 1024
#define THR_MAIN  (NC * 32)           // 160

__device__ float4 g_part[GRID_MAIN][NC][64];   // 5 MB static scratch

#define FM4(a, v)  { a.x = fmaxf(a.x, v.x); a.y = fmaxf(a.y, v.y); \
                     a.z = fmaxf(a.z, v.z); a.w = fmaxf(a.w, v.w); }

__global__ __launch_bounds__(THR_MAIN, 7)
void pool_main(const float* __restrict__ x, const int* __restrict__ labels)
{
    __shared__ int s_idx[NC][QROWS];

    const int tid  = threadIdx.x;
    const int w    = tid >> 5;         // class-warp 0..4
    const int lane = tid & 31;
    const int c    = w + 1;
    const int q    = blockIdx.x & (NQ - 1);
    const int b    = blockIdx.x >> 2;
    const int row0 = b * LSEQ + q * QROWS;

    // ---- Per-warp gather of own-class local row indices (ascending).
    const int* lab = labels + row0;
    const unsigned below = (1u << lane) - 1u;
    int cnt = 0;
#pragma unroll
    for (int k = 0; k < QROWS / 32; k++) {
        const int  l = lane + 32 * k;
        const bool f = (lab[l] == c);
        const unsigned m = __ballot_sync(0xffffffffu, f);
        if (f) s_idx[w][cnt + __popc(m & below)] = l;
        cnt += __popc(m);              // warp-uniform
    }
    __syncwarp();

    // ---- Stream own rows: lane owns float4 cols lane and 32+lane (full 1KB row
    //      per warp); 2 rows / 4 LDG.128 per iteration (MLP 4, proven enough).
    const float4* __restrict__ X4 = (const float4*)x + (size_t)row0 * (DDIM / 4);
    float4 a0 = make_float4(0.f, 0.f, 0.f, 0.f), a1 = a0;

    int j = 0;
    for (; j + 1 < cnt; j += 2) {
        const int l0 = s_idx[w][j];
        const int l1 = s_idx[w][j + 1];
        const float4 v0 = X4[(size_t)l0 * 64 + lane];
        const float4 u0 = X4[(size_t)l0 * 64 + 32 + lane];
        const float4 v1 = X4[(size_t)l1 * 64 + lane];
        const float4 u1 = X4[(size_t)l1 * 64 + 32 + lane];
        FM4(a0, v0); FM4(a1, u0);
        FM4(a0, v1); FM4(a1, u1);
    }
    if (j < cnt) {
        const int l = s_idx[w][j];
        const float4 v = X4[(size_t)l * 64 + lane];
        const float4 u = X4[(size_t)l * 64 + 32 + lane];
        FM4(a0, v); FM4(a1, u);
    }

    g_part[blockIdx.x][w][lane]      = a0;
    g_part[blockIdx.x][w][32 + lane] = a1;
}

__global__ void pool_reduce(float4* __restrict__ out)
{
    // One thread per output float4: i = b*320 + c*64 + col  (matches out layout).
    const int i   = blockIdx.x * 256 + threadIdx.x;
    const int col = i & 63;
    const int c   = (i >> 6) % NC;
    const int b   = i / (NC * 64);

    float4 m = g_part[b * NQ][c][col];
#pragma unroll
    for (int qq = 1; qq < NQ; qq++) {
        const float4 v = g_part[b * NQ + qq][c][col];
        FM4(m, v);
    }
    out[i] = m;
}

extern "C" void kernel_launch(void* const* d_in, const int* in_sizes, int n_in,
                              void* d_out, int out_size)
{
    const float* x      = (const float*)d_in[0];
    const int*   labels = (const int*)d_in[1];
    float4*      out    = (float4*)d_out;

    pool_main<<<GRID_MAIN, THR_MAIN>>>(x, labels);
    pool_reduce<<<(BATCH * NC * 64) / 256, 256>>>(out);
}

// round 14
// speedup vs baseline: 1.0819x; 1.0819x over previous
#include <cuda_runtime.h>

// embedding_pooling: out[b, (c-1)*256 + d] = relu(max_{l: label[b,l]==c} x[b,l,d]), empty->0
//  - relu + empty-case == fmax chain initialized at 0.
//  - Labels are int32 on device (proven R2 fail / R3 pass).
//
// Page-dense gather (R13 main, best streaming phase measured ~21.3us):
// CTA = quarter batch row (128 rows = 128KB), 5 warps, warp w owns class w+1.
// Each warp ballot-gathers its own row list (no block syncs) and streams it;
// the 5 warps' requests form a sliding ~8KB window covering every non-zero
// row in ascending order -> near-linear DRAM page behavior while skipping
// label-0 rows (107MB instead of 128MB).
// Quarter results merged straight into out via scalar atomicMax on int-viewed
// floats (all candidates >= 0; out zero-filled first; int order == float
// order for non-negative floats). No scratch, no reduce kernel.

#define BATCH 256
#define LSEQ  512
#define DDIM  256
#define NC    5
#define QROWS 128
#define NQ    (LSEQ / QROWS)          // 4
#define GRID_MAIN (BATCH * NQ)        // 1024
#define THR_MAIN  (NC * 32)           // 160
#define OUT_ELEMS (BATCH * NC * DDIM) // 327680

#define FM4(a, v)  { a.x = fmaxf(a.x, v.x); a.y = fmaxf(a.y, v.y); \
                     a.z = fmaxf(a.z, v.z); a.w = fmaxf(a.w, v.w); }

__global__ void zero_out_kernel(int4* __restrict__ out)
{
    // 327680 ints = 81920 int4; 320 blocks x 256 threads.
    out[blockIdx.x * 256 + threadIdx.x] = make_int4(0, 0, 0, 0);
}

__global__ __launch_bounds__(THR_MAIN, 7)
void pool_main(const float* __restrict__ x, const int* __restrict__ labels,
               int* __restrict__ out)
{
    __shared__ int s_idx[NC][QROWS];

    const int tid  = threadIdx.x;
    const int w    = tid >> 5;         // class-warp 0..4
    const int lane = tid & 31;
    const int c    = w + 1;
    const int q    = blockIdx.x & (NQ - 1);
    const int b    = blockIdx.x >> 2;
    const int row0 = b * LSEQ + q * QROWS;

    // ---- Per-warp gather of own-class local row indices (ascending).
    const int* lab = labels + row0;
    const unsigned below = (1u << lane) - 1u;
    int cnt = 0;
#pragma unroll
    for (int k = 0; k < QROWS / 32; k++) {
        const int  l = lane + 32 * k;
        const bool f = (lab[l] == c);
        const unsigned m = __ballot_sync(0xffffffffu, f);
        if (f) s_idx[w][cnt + __popc(m & below)] = l;
        cnt += __popc(m);              // warp-uniform
    }
    __syncwarp();

    // ---- Stream own rows: lane owns float4 cols lane and 32+lane;
    //      2 rows / 4 LDG.128 per iteration.
    const float4* __restrict__ X4 = (const float4*)x + (size_t)row0 * (DDIM / 4);
    float4 a0 = make_float4(0.f, 0.f, 0.f, 0.f), a1 = a0;

    int j = 0;
    for (; j + 1 < cnt; j += 2) {
        const int l0 = s_idx[w][j];
        const int l1 = s_idx[w][j + 1];
        const float4 v0 = X4[(size_t)l0 * 64 + lane];
        const float4 u0 = X4[(size_t)l0 * 64 + 32 + lane];
        const float4 v1 = X4[(size_t)l1 * 64 + lane];
        const float4 u1 = X4[(size_t)l1 * 64 + 32 + lane];
        FM4(a0, v0); FM4(a1, u0);
        FM4(a0, v1); FM4(a1, u1);
    }
    if (j < cnt) {
        const int l = s_idx[w][j];
        const float4 v = X4[(size_t)l * 64 + lane];
        const float4 u = X4[(size_t)l * 64 + 32 + lane];
        FM4(a0, v); FM4(a1, u);
    }

    // ---- Merge quarters: 8 scalar atomicMax per lane, distinct addresses.
    //      out[b][(c-1)*256 + d]; a0 -> d = 4*lane..  a1 -> d = 128 + 4*lane..
    int* o = out + (size_t)b * (NC * DDIM) + w * DDIM;
    atomicMax(o + 4 * lane + 0,       __float_as_int(a0.x));
    atomicMax(o + 4 * lane + 1,       __float_as_int(a0.y));
    atomicMax(o + 4 * lane + 2,       __float_as_int(a0.z));
    atomicMax(o + 4 * lane + 3,       __float_as_int(a0.w));
    atomicMax(o + 128 + 4 * lane + 0, __float_as_int(a1.x));
    atomicMax(o + 128 + 4 * lane + 1, __float_as_int(a1.y));
    atomicMax(o + 128 + 4 * lane + 2, __float_as_int(a1.z));
    atomicMax(o + 128 + 4 * lane + 3, __float_as_int(a1.w));
}

extern "C" void kernel_launch(void* const* d_in, const int* in_sizes, int n_in,
                              void* d_out, int out_size)
{
    const float* x      = (const float*)d_in[0];
    const int*   labels = (const int*)d_in[1];
    int*         out    = (int*)d_out;

    zero_out_kernel<<<OUT_ELEMS / 4 / 256, 256>>>((int4*)out);
    pool_main<<<GRID_MAIN, THR_MAIN>>>(x, labels, out);
}

// round 16
// speedup vs baseline: 1.1818x; 1.0923x over previous
#include <cuda_runtime.h>

// embedding_pooling: out[b, (c-1)*256 + d] = relu(max_{l: label[b,l]==c} x[b,l,d]), empty->0
//  - relu + empty-case == fmax chain initialized at 0.
//  - Labels are int32 on device (proven R2 fail / R3 pass).
//
// Best-measured structure (R7/R12, 22.56us timed x2): 1280 CTAs x 128 thr,
// single resident wave, per-CTA ballot-ordered gather of matching l's, then
// team-strided float4 streaming max with 8 independent LDG.128 in flight.
// This round's single change: __ldcs streaming hint on x loads (use-once data;
// keep it out of L2 so fills don't contend with demand traffic). Labels keep
// default caching (reused by the 5 class-CTAs of each b).

#define BATCH 256
#define LSEQ  512
#define DDIM  256
#define NC    5
#define NW    4

#define FM4(a, v)  { a.x = fmaxf(a.x, v.x); a.y = fmaxf(a.y, v.y); \
                     a.z = fmaxf(a.z, v.z); a.w = fmaxf(a.w, v.w); }

__global__ __launch_bounds__(128, 9)
void embedding_pooling_kernel(const float* __restrict__ x,
                              const int* __restrict__ labels,
                              float* __restrict__ out)
{
    __shared__ int    s_idx[LSEQ];
    __shared__ int    s_base[17];
    __shared__ float4 s_red[2][64];

    const int tid  = threadIdx.x;
    const int w    = tid >> 5;
    const int lane = tid & 31;
    const int b    = blockIdx.x / NC;
    const int c    = (blockIdx.x % NC) + 1;

    // ---- Phase 1: ballot-ordered compaction of l with label == c.
    const int* lab_row = labels + (size_t)b * LSEQ;
    bool     f[4];
    unsigned m[4];
#pragma unroll
    for (int k = 0; k < 4; k++) {
        f[k] = (lab_row[tid + 128 * k] == c);
        m[k] = __ballot_sync(0xffffffffu, f[k]);
    }
    if (lane == 0) {
#pragma unroll
        for (int k = 0; k < 4; k++)
            s_base[k * NW + w] = __popc(m[k]);
    }
    __syncthreads();
    if (tid == 0) {
        int acc = 0;
#pragma unroll
        for (int i = 0; i < 16; i++) {
            const int t = s_base[i];
            s_base[i] = acc;
            acc += t;
        }
        s_base[16] = acc;
    }
    __syncthreads();
    const unsigned below = (1u << lane) - 1u;
#pragma unroll
    for (int k = 0; k < 4; k++)
        if (f[k]) s_idx[s_base[k * NW + w] + __popc(m[k] & below)] = tid + 128 * k;
    __syncthreads();
    const int n = s_base[16];

    // ---- Phase 2: team-strided max (team = 64 thr owns rows j == team mod 2;
    //      thread owns one float4 column). 8 streaming LDG.128 in flight.
    const int team = tid >> 6;
    const int col  = tid & 63;
    const float4* __restrict__ Xb = (const float4*)x + (size_t)b * LSEQ * (DDIM / 4);

    float4 acc = make_float4(0.f, 0.f, 0.f, 0.f);
    int j = team;
    for (; j + 14 < n; j += 16) {
        const int l0 = s_idx[j];
        const int l1 = s_idx[j +  2];
        const int l2 = s_idx[j +  4];
        const int l3 = s_idx[j +  6];
        const int l4 = s_idx[j +  8];
        const int l5 = s_idx[j + 10];
        const int l6 = s_idx[j + 12];
        const int l7 = s_idx[j + 14];
        const float4 v0 = __ldcs(Xb + (size_t)l0 * 64 + col);
        const float4 v1 = __ldcs(Xb + (size_t)l1 * 64 + col);
        const float4 v2 = __ldcs(Xb + (size_t)l2 * 64 + col);
        const float4 v3 = __ldcs(Xb + (size_t)l3 * 64 + col);
        const float4 v4 = __ldcs(Xb + (size_t)l4 * 64 + col);
        const float4 v5 = __ldcs(Xb + (size_t)l5 * 64 + col);
        const float4 v6 = __ldcs(Xb + (size_t)l6 * 64 + col);
        const float4 v7 = __ldcs(Xb + (size_t)l7 * 64 + col);
        FM4(acc, v0); FM4(acc, v1); FM4(acc, v2); FM4(acc, v3);
        FM4(acc, v4); FM4(acc, v5); FM4(acc, v6); FM4(acc, v7);
    }
    for (; j < n; j += 2) {
        const float4 v = __ldcs(Xb + (size_t)s_idx[j] * 64 + col);
        FM4(acc, v);
    }

    s_red[team][col] = acc;
    __syncthreads();

    // ---- Phase 3: fold the 2 teams; one float4 store per column.
    if (tid < 64) {
        float4 mm = s_red[0][tid];
        const float4 v = s_red[1][tid];
        FM4(mm, v);
        float4* O4 = (float4*)out;
        O4[(size_t)b * (NC * (DDIM / 4)) + (size_t)(c - 1) * (DDIM / 4) + tid] = mm;
    }
}

extern "C" void kernel_launch(void* const* d_in, const int* in_sizes, int n_in,
                              void* d_out, int out_size)
{
    const float* x      = (const float*)d_in[0];
    const int*   labels = (const int*)d_in[1];
    float*       out    = (float*)d_out;

    embedding_pooling_kernel<<<BATCH * NC, 128>>>(x, labels, out);
}